// round 16
// baseline (speedup 1.0000x reference)
#include <cuda_runtime.h>
#include <cuda_fp16.h>
#include <mma.h>

using namespace nvcuda;

#define N     16384
#define C     64
#define KNN   16
#define O     256       // C*R
#define QB    64        // queries per block
#define TJ    128       // j-tile rows
#define NITER (N / TJ)
#define NB    32        // points per block in ab_kernel
#define FINF  3.4e38f
#define FULLM 0xffffffffu
#define MARG  2.5e-3f   // >= 2^-9 (proved bound) + fp32 slop

#define BP    72        // half pitch for BH / A-stage (144B rows, ldm mult of 8)
#define DPF   132       // float pitch for D tile (mult of 4)

// ---- dynamic smem layout ---------------------------------------------------
#define SM_BH    0                    // 128*72*2  = 18432
#define SM_D32   18432                // 64*132*4  = 33792 (A-stage scratch in prologue)
#define SM_SQ    52224                // 2*128*4   = 1024
#define SM_NRM   53248                // 2*128*4   = 1024
#define SM_LK    54272                // 64*16*4   = 4096
#define SM_LI    58368                // 4096
#define SM_TOTAL 62464

__device__ float  g_sq[N];
__device__ float  g_nrm[N];
__device__ __half g_qhi[N * C];   // fp16(x)    A side
__device__ __half g_khi[N * C];   // fp16(-2x)  B side
__device__ float  g_A[N * O];
__device__ float  g_B[N * O];
__device__ int    g_idx[N * KNN];

// ---------------------------------------------------------------------------
// squared norms, norms, fp16 hi parts: one warp per row
// ---------------------------------------------------------------------------
__global__ void sq_kernel(const float* __restrict__ x) {
    int row  = blockIdx.x * 8 + (threadIdx.x >> 5);
    int lane = threadIdx.x & 31;
    float s = 0.f;
    #pragma unroll
    for (int h = 0; h < 2; h++) {
        float v = x[row * C + 32 * h + lane];
        g_qhi[row * C + 32 * h + lane] = __float2half_rn(v);
        g_khi[row * C + 32 * h + lane] = __float2half_rn(-2.f * v);
        s += v * v;
    }
    #pragma unroll
    for (int off = 16; off; off >>= 1)
        s += __shfl_down_sync(FULLM, s, off);
    if (lane == 0) { g_sq[row] = s; g_nrm[row] = sqrtf(s); }
}

// ---------------------------------------------------------------------------
// A = x @ (W_top - W_bot) + b ;  B = x @ W_bot
// ---------------------------------------------------------------------------
__global__ __launch_bounds__(256) void ab_kernel(const float* __restrict__ x,
                                                 const float* __restrict__ W,
                                                 const float* __restrict__ b) {
    __shared__ float xs[NB][C + 1];
    const int o  = threadIdx.x;
    const int nb = blockIdx.x * NB;
    #pragma unroll
    for (int it = 0; it < (NB * C) / 256; it++) {
        int linear = threadIdx.x + 256 * it;
        xs[linear >> 6][linear & 63] = x[nb * C + linear];
    }
    __syncthreads();
    float accA[NB], accB[NB];
    float bb = b[o];
    #pragma unroll
    for (int i = 0; i < NB; i++) { accA[i] = bb; accB[i] = 0.f; }
    for (int c = 0; c < C; c++) {
        float wt = W[c * O + o];
        float wb = W[(c + C) * O + o];
        float wd = wt - wb;
        #pragma unroll
        for (int i = 0; i < NB; i++) {
            float xv = xs[i][c];
            accA[i] = fmaf(xv, wd, accA[i]);
            accB[i] = fmaf(xv, wb, accB[i]);
        }
    }
    #pragma unroll
    for (int i = 0; i < NB; i++) {
        g_A[(nb + i) * O + o] = accA[i];
        g_B[(nb + i) * O + o] = accB[i];
    }
}

// ---------------------------------------------------------------------------
// knn: approx D = fp16(x_i)·fp16(-2x_j) via HMMA (fp32 acc); candidates
// admitted when approx_key - MARG*nrm_i*nrm_j < cm (cm = 16th EXACT key),
// then rescreened with an exact fp32 dot. Selection provably exact.
// 512 threads = 16 warps. Warp w: GEMM m-tile w>>2, n-tiles (w&3), (w&3)+4;
// selection for queries [w*4, w*4+4).
// ---------------------------------------------------------------------------
__global__ __launch_bounds__(512, 1) void knn_kernel(const float* __restrict__ x) {
    extern __shared__ __align__(16) char smem[];
    __half* BH   = (__half*)(smem + SM_BH);
    float*  D32  = (float*) (smem + SM_D32);
    float*  SQs  = (float*) (smem + SM_SQ);
    float*  NRMs = (float*) (smem + SM_NRM);
    float*  LK   = (float*) (smem + SM_LK);
    int*    LI   = (int*)   (smem + SM_LI);

    const int tid  = threadIdx.x;
    const int w    = tid >> 5;
    const int lane = tid & 31;
    const int mt   = w >> 2;
    const int qBase = blockIdx.x * QB;
    const int t16  = lane & 15;

    // ---- prologue: stage A (qhi) into D32 scratch, load frags --------------
    {
        __half* AH = (__half*)D32;
        const uint4* src = (const uint4*)(g_qhi + (size_t)qBase * C);
        uint4 v = src[tid];                       // 512 u4 = 64 rows x 8
        *((uint4*)(AH + (tid >> 3) * BP + (tid & 7) * 8)) = v;
    }
    __syncthreads();

    wmma::fragment<wmma::matrix_a, 16, 16, 16, __half, wmma::row_major> a_hi[4];
    {
        const __half* AH = (const __half*)D32;
        #pragma unroll
        for (int kk = 0; kk < 4; kk++)
            wmma::load_matrix_sync(a_hi[kk], AH + (mt * 16) * BP + kk * 16, BP);
    }

    // ---- per-warp query caches ---------------------------------------------
    float xi0[4], xi1[4], cfi[4], cm[4];
    #pragma unroll
    for (int qi = 0; qi < 4; qi++) {
        int qg = qBase + w * 4 + qi;
        xi0[qi] = x[qg * C + lane];
        xi1[qi] = x[qg * C + 32 + lane];
        cfi[qi] = MARG * g_nrm[qg];
        cm[qi]  = FINF;
    }
    if (lane < KNN) {
        #pragma unroll
        for (int qi = 0; qi < 4; qi++) {
            LK[(w * 4 + qi) * KNN + lane] = FINF;
            LI[(w * 4 + qi) * KNN + lane] = 0;
        }
    }

    // ---- prefetch tile 0 ---------------------------------------------------
    uint4 pfh0, pfh1; float pfs, pfn;
    {
        const uint4* src = (const uint4*)g_khi;   // 1024 u4 = 128 rows x 8
        pfh0 = src[tid];
        pfh1 = src[tid + 512];
        if (tid < TJ) { pfs = g_sq[tid]; pfn = g_nrm[tid]; }
    }
    __syncthreads();   // frags loaded: D32 scratch free for GEMM writes

    // ---- main loop ---------------------------------------------------------
    for (int t = 0; t < NITER; t++) {
        const int buf = t & 1;
        const int jt  = t * TJ;

        // commit prefetched B (last read: GEMM(t-1), behind bar2(t-1))
        {
            int i0 = tid, i1 = tid + 512;
            *((uint4*)(BH + (i0 >> 3) * BP + (i0 & 7) * 8)) = pfh0;
            *((uint4*)(BH + (i1 >> 3) * BP + (i1 & 7) * 8)) = pfh1;
        }
        if (tid < TJ) { SQs[buf * TJ + tid] = pfs; NRMs[buf * TJ + tid] = pfn; }
        __syncthreads();

        // prefetch t+1 (in flight across GEMM + selection)
        {
            int njt = (jt + TJ < N) ? jt + TJ : 0;
            const uint4* src = (const uint4*)(g_khi + (size_t)njt * C);
            pfh0 = src[tid];
            pfh1 = src[tid + 512];
            if (tid < TJ) { pfs = g_sq[njt + tid]; pfn = g_nrm[njt + tid]; }
        }

        // GEMM: warp does 2 n-tiles of 16x16, 4 k-steps, fp32 acc
        #pragma unroll
        for (int half = 0; half < 2; half++) {
            const int nt2 = (w & 3) + 4 * half;
            wmma::fragment<wmma::accumulator, 16, 16, 16, float> acc;
            wmma::fill_fragment(acc, 0.f);
            #pragma unroll
            for (int kk = 0; kk < 4; kk++) {
                wmma::fragment<wmma::matrix_b, 16, 16, 16, __half, wmma::col_major> bf;
                wmma::load_matrix_sync(bf, BH + (nt2 * 16) * BP + kk * 16, BP);
                wmma::mma_sync(acc, a_hi[kk], bf, acc);
            }
            wmma::store_matrix_sync(D32 + (mt * 16) * DPF + nt2 * 16, acc, DPF,
                                    wmma::mem_row_major);
        }
        __syncthreads();

        // selection: warp w owns queries w*4..w*4+3; j = lane + 32g, g<4
        #pragma unroll
        for (int qi = 0; qi < 4; qi++) {
            const int q  = w * 4 + qi;
            const int qg = qBase + q;
            float slack[4];
            #pragma unroll
            for (int g = 0; g < 4; g++) {
                int jj = lane + 32 * g;
                float ak = D32[q * DPF + jj] + SQs[buf * TJ + jj];
                slack[g] = ak - cfi[qi] * NRMs[buf * TJ + jj];
                if (jt + jj == qg) slack[g] = FINF;        // exclude self
            }
            float kmin = fminf(fminf(slack[0], slack[1]),
                               fminf(slack[2], slack[3]));
            if (__ballot_sync(FULLM, kmin < cm[qi])) {
                #pragma unroll
                for (int g = 0; g < 4; g++) {
                    unsigned bm = __ballot_sync(FULLM, slack[g] < cm[qi]);
                    while (bm) {
                        int src = __ffs(bm) - 1;
                        bm &= bm - 1;
                        float cs = __shfl_sync(FULLM, slack[g], src);
                        if (cs < cm[qi]) {                 // re-check vs updated cm
                            int cj = jt + src + 32 * g;
                            // exact fp32 key, warp-parallel
                            float xj0 = x[cj * C + lane];
                            float xj1 = x[cj * C + 32 + lane];
                            float dp  = fmaf(xi0[qi], xj0, xi1[qi] * xj1);
                            #pragma unroll
                            for (int off = 16; off; off >>= 1)
                                dp += __shfl_xor_sync(FULLM, dp, off);
                            float ek = fmaf(-2.f, dp, SQs[buf * TJ + (cj - jt)]);
                            if (ek < cm[qi]) {
                                float lv = (lane < KNN) ? LK[q * KNN + t16] : -FINF;
                                int   lp = t16;
                                #pragma unroll
                                for (int off = 8; off; off >>= 1) {
                                    float ov = __shfl_xor_sync(FULLM, lv, off);
                                    int   op = __shfl_xor_sync(FULLM, lp, off);
                                    if (ov > lv || (ov == lv && op < lp)) { lv = ov; lp = op; }
                                }
                                int mp = __shfl_sync(FULLM, lp, 0);
                                if (lane == 0) { LK[q * KNN + mp] = ek; LI[q * KNN + mp] = cj; }
                                __syncwarp(FULLM);
                                float nv = (lane < KNN) ? LK[q * KNN + t16] : -FINF;
                                #pragma unroll
                                for (int off = 8; off; off >>= 1)
                                    nv = fmaxf(nv, __shfl_xor_sync(FULLM, nv, off));
                                cm[qi] = __shfl_sync(FULLM, nv, 0);
                            }
                        }
                    }
                }
            }
        }
    }

    // ---- write out lists (order irrelevant: feeds max-pool) ----------------
    __syncwarp(FULLM);
    if (lane < KNN) {
        #pragma unroll
        for (int qi = 0; qi < 4; qi++)
            g_idx[(qBase + w * 4 + qi) * KNN + lane] = LI[(w * 4 + qi) * KNN + lane];
    }
}

// ---------------------------------------------------------------------------
// out[n, o] = relu(A[n,o] + max_k B[idx[n,k], o]) ; permuted store
// ---------------------------------------------------------------------------
__global__ void out_kernel(float* __restrict__ y) {
    __shared__ int idxs[KNN];
    int n = blockIdx.x;
    int o = threadIdx.x;
    if (o < KNN) idxs[o] = g_idx[n * KNN + o];
    __syncthreads();
    float m = -FINF;
    #pragma unroll
    for (int k = 0; k < KNN; k++)
        m = fmaxf(m, g_B[idxs[k] * O + o]);
    float v = fmaxf(g_A[n * O + o] + m, 0.f);
    y[(n * 4 + (o & 3)) * C + (o >> 2)] = v;
}

// ---------------------------------------------------------------------------
extern "C" void kernel_launch(void* const* d_in, const int* in_sizes, int n_in,
                              void* d_out, int out_size) {
    const float* x = (const float*)d_in[0];
    const float* W = (const float*)d_in[1];
    const float* b = (const float*)d_in[2];
    float* y = (float*)d_out;

    static int configured = 0;
    if (!configured) {
        cudaFuncSetAttribute(knn_kernel,
                             cudaFuncAttributeMaxDynamicSharedMemorySize, SM_TOTAL);
        configured = 1;
    }

    sq_kernel <<<N / 8, 256>>>(x);
    knn_kernel<<<N / QB, 512, SM_TOTAL>>>(x);
    ab_kernel <<<N / NB, 256>>>(x, W, b);
    out_kernel<<<N, 256>>>(y);
}